// round 9
// baseline (speedup 1.0000x reference)
#include <cuda_runtime.h>
#include <cstdint>

#define D        512
#define NROWS    65536
#define MCODES   4096
#define BM       128
#define BN       64
#define BK       32
#define NKC      (D / BK)        // 16
#define NT_R     (NROWS / BM)    // 512
#define NT_C     (MCODES / BN)   // 64
#define NGRP     NT_C            // one 64-col group per ct
#define THRESH   0.05f

// ---------------- scratch (device globals) -----------------------------------
#define A_BLK 4096               // 128 rows x 32 int8 per (rt,kc)
#define B_BLK 2048               // 64 rows x 32 int8 per (ct,kc)
__device__ __align__(128) unsigned char qAh[(size_t)NT_R * NKC * A_BLK]; // 32MB
__device__ __align__(128) unsigned char qAl[(size_t)NT_R * NKC * A_BLK]; // 32MB
__device__ __align__(128) unsigned char qBh[(size_t)NT_C * NKC * B_BLK]; // 2MB
__device__ __align__(128) unsigned char qBl[(size_t)NT_C * NKC * B_BLK]; // 2MB

__device__ float              g_sA[NROWS];
__device__ float              g_sB[MCODES];
__device__ float              g_halfcsq[MCODES];
__device__ unsigned long long g_cand[(size_t)NROWS * NGRP * 2];  // 67MB
__device__ int                g_idx[NROWS];
__device__ int                g_flag_count;
__device__ int                g_flag_list[NROWS];

// ---------------- helpers ----------------------------------------------------
__device__ __forceinline__ unsigned int f2sortable(float f) {
    unsigned int u = __float_as_uint(f);
    return (u & 0x80000000u) ? ~u : (u | 0x80000000u);
}
__device__ __forceinline__ float sortable2f(unsigned int u) {
    unsigned int b = (u & 0x80000000u) ? (u ^ 0x80000000u) : ~u;
    return __uint_as_float(b);
}
__device__ __forceinline__ unsigned long long packSI(float s, int col) {
    return ((unsigned long long)f2sortable(s) << 32) |
           (unsigned long long)(0xFFFFFFFFu - (unsigned)col);
}
__device__ __forceinline__ void top2merge(unsigned long long& b1, unsigned long long& b2,
                                          unsigned long long o1, unsigned long long o2) {
    if (o1 > b1) { b2 = (b1 > o2) ? b1 : o2; b1 = o1; }
    else if (o1 > b2) { b2 = o1; }
}
__device__ __forceinline__ uint32_t smem_u32(const void* p) {
    uint32_t a;
    asm("{ .reg .u64 t; cvta.to.shared.u64 t, %1; cvt.u32.u64 %0, t; }" : "=r"(a) : "l"(p));
    return a;
}

// ---------------- cp.async / ldmatrix / mma ----------------------------------
__device__ __forceinline__ void cp16(uint32_t dst, const void* src) {
    asm volatile("cp.async.cg.shared.global [%0], [%1], 16;" :: "r"(dst), "l"(src) : "memory");
}
#define CP_COMMIT() asm volatile("cp.async.commit_group;" ::: "memory")
#define CP_WAIT(N)  asm volatile("cp.async.wait_group %0;" :: "n"(N) : "memory")

#define LDM4(r, addr) \
    asm volatile("ldmatrix.sync.aligned.m8n8.x4.shared.b16 {%0,%1,%2,%3}, [%4];" \
        : "=r"((r)[0]), "=r"((r)[1]), "=r"((r)[2]), "=r"((r)[3]) : "r"(addr))

#define MMAI8(d, a, b0_, b1_) \
    asm volatile("mma.sync.aligned.m16n8k32.row.col.s32.s8.s8.s32 " \
        "{%0,%1,%2,%3},{%4,%5,%6,%7},{%8,%9},{%0,%1,%2,%3};" \
        : "+r"((d)[0]), "+r"((d)[1]), "+r"((d)[2]), "+r"((d)[3]) \
        : "r"((a)[0]), "r"((a)[1]), "r"((a)[2]), "r"((a)[3]), "r"(b0_), "r"(b1_))

// ---------------- stage layout -----------------------------------------------
#define ST_AH 0
#define ST_AL 4096
#define ST_BH 8192
#define ST_BL 10240
#define STG   12288
#define NSTAGE 4
#define SMEM_TOTAL (NSTAGE * STG)   // 49152

// ---------------- quantization -----------------------------------------------
__device__ __forceinline__ uint32_t pack4(int q0, int q1, int q2, int q3) {
    return (uint32_t)(q0 & 0xFF) | ((uint32_t)(q1 & 0xFF) << 8) |
           ((uint32_t)(q2 & 0xFF) << 16) | ((uint32_t)(q3 & 0xFF) << 24);
}

template<int RSHIFT, int BLKSZ>
__device__ __forceinline__ void quant_row(const float* __restrict__ X, int row,
                                          unsigned char* __restrict__ ph,
                                          unsigned char* __restrict__ pl,
                                          float* __restrict__ scale_out,
                                          float* __restrict__ halfcsq_out) {
    const int lane = threadIdx.x & 31;
    const float4* xp = (const float4*)(X + (size_t)row * D + lane * 16);
    float4 v[4];
    float amax = 0.f, ssq = 0.f;
    #pragma unroll
    for (int i = 0; i < 4; ++i) {
        v[i] = xp[i];
        amax = fmaxf(amax, fmaxf(fmaxf(fabsf(v[i].x), fabsf(v[i].y)),
                                 fmaxf(fabsf(v[i].z), fabsf(v[i].w))));
        if (halfcsq_out)
            ssq += v[i].x * v[i].x + v[i].y * v[i].y + v[i].z * v[i].z + v[i].w * v[i].w;
    }
    #pragma unroll
    for (int o = 16; o > 0; o >>= 1) {
        amax = fmaxf(amax, __shfl_xor_sync(0xffffffffu, amax, o));
        if (halfcsq_out) ssq += __shfl_xor_sync(0xffffffffu, ssq, o);
    }
    amax = fmaxf(amax, 1e-30f);
    const float inv = 127.f / amax;
    uint32_t H[4], L[4];
    #pragma unroll
    for (int i = 0; i < 4; ++i) {
        float f[4] = {v[i].x, v[i].y, v[i].z, v[i].w};
        int qh[4], ql[4];
        #pragma unroll
        for (int j = 0; j < 4; ++j) {
            float t = f[j] * inv;
            qh[j] = __float2int_rn(t);
            qh[j] = max(-127, min(127, qh[j]));
            float rh = t - (float)qh[j];
            ql[j] = __float2int_rn(rh * 128.f);
        }
        H[i] = pack4(qh[0], qh[1], qh[2], qh[3]);
        L[i] = pack4(ql[0], ql[1], ql[2], ql[3]);
    }
    const int rt  = row >> RSHIFT;
    const int rIn = row & ((1 << RSHIFT) - 1);
    const int kc  = lane >> 1;
    const int c   = lane & 1;
    const size_t off = (size_t)(rt * NKC + kc) * BLKSZ +
                       (size_t)(c * (1 << RSHIFT) + rIn) * 16;
    *(uint4*)(ph + off) = make_uint4(H[0], H[1], H[2], H[3]);
    *(uint4*)(pl + off) = make_uint4(L[0], L[1], L[2], L[3]);
    if (lane == 0) {
        scale_out[row] = amax / 127.f;
        if (halfcsq_out) halfcsq_out[row] = 0.5f * ssq;
    }
}

__global__ void k_quant_a(const float* __restrict__ A) {
    int row = blockIdx.x * 8 + (threadIdx.x >> 5);
    if (row < NROWS) quant_row<7, A_BLK>(A, row, qAh, qAl, g_sA, nullptr);
}
__global__ void k_quant_b(const float* __restrict__ B) {
    int row = blockIdx.x * 8 + (threadIdx.x >> 5);
    if (row < MCODES) quant_row<6, B_BLK>(B, row, qBh, qBl, g_sB, g_halfcsq);
}

__global__ void k_init() { if (threadIdx.x == 0) g_flag_count = 0; }

// ---------------- main GEMM: int8 double-digit, 3 products -------------------
// 256 thr, 2 CTAs/SM. Warp grid 2x4: warp tile 64 rows x 16 cols.
// m processed in pairs with product-major mma order: same-acc reuse gap = 4 mmas.
__global__ void __launch_bounds__(256, 2)
k_gemm() {
    extern __shared__ char smem[];
    const uint32_t sb = smem_u32(smem);
    const int tid  = threadIdx.x;
    const int wid  = tid >> 5;
    const int lane = tid & 31;
    const int ct = blockIdx.x;           // 0..63 fastest -> B fully L2-resident
    const int rt = blockIdx.y;           // 0..511
    const int wr = wid >> 2;             // 0..1 -> rows wr*64..+63
    const int wc = wid & 3;              // 0..3 -> cols wc*16..+15

    const unsigned char* aH = qAh + (size_t)(rt * NKC) * A_BLK;
    const unsigned char* aL = qAl + (size_t)(rt * NKC) * A_BLK;
    const unsigned char* bH = qBh + (size_t)(ct * NKC) * B_BLK;
    const unsigned char* bL = qBl + (size_t)(ct * NKC) * B_BLK;

    auto load_stage = [&](int kc) {
        const uint32_t st = sb + (kc & (NSTAGE - 1)) * STG;
        const uint32_t o = tid * 16;
        cp16(st + ST_AH + o, aH + (size_t)kc * A_BLK + o);
        cp16(st + ST_AL + o, aL + (size_t)kc * A_BLK + o);
        if (tid < 128) cp16(st + ST_BH + o, bH + (size_t)kc * B_BLK + o);
        else           cp16(st + ST_BL + (o - 2048), bL + (size_t)kc * B_BLK + (o - 2048));
    };

    // ldmatrix lane address pieces
    const int mtx = lane >> 3;
    const uint32_t aOff = (uint32_t)((mtx >> 1) * 2048 +
                          (wr * 64 + (mtx & 1) * 8 + (lane & 7)) * 16);
    const uint32_t bOff = (uint32_t)((mtx & 1) * 1024 +
                          (wc * 16 + (mtx >> 1) * 8 + (lane & 7)) * 16);

    int acc1[4][2][4], acc2[4][2][4];
    #pragma unroll
    for (int m = 0; m < 4; ++m)
        #pragma unroll
        for (int n = 0; n < 2; ++n)
            #pragma unroll
            for (int q = 0; q < 4; ++q) { acc1[m][n][q] = 0; acc2[m][n][q] = 0; }

    load_stage(0); CP_COMMIT();
    load_stage(1); CP_COMMIT();
    load_stage(2); CP_COMMIT();

    #pragma unroll 1
    for (int kc = 0; kc < NKC; ++kc) {
        if (kc < NKC - 2)       { CP_WAIT(2); }
        else if (kc == NKC - 2) { CP_WAIT(1); }
        else                    { CP_WAIT(0); }
        __syncthreads();
        if (kc + 3 < NKC) { load_stage(kc + 3); CP_COMMIT(); }

        const uint32_t st = sb + (kc & (NSTAGE - 1)) * STG;
        uint32_t bh[4], bl[4];
        LDM4(bh, st + ST_BH + bOff);
        LDM4(bl, st + ST_BL + bOff);
        #pragma unroll
        for (int mp = 0; mp < 2; ++mp) {          // m pair: {2mp, 2mp+1}
            const int m0 = 2 * mp, m1 = 2 * mp + 1;
            uint32_t ah0[4], al0[4], ah1[4], al1[4];
            const uint32_t ad0 = st + aOff + (uint32_t)(m0 * 256);
            const uint32_t ad1 = st + aOff + (uint32_t)(m1 * 256);
            LDM4(ah0, ad0 + ST_AH);
            LDM4(al0, ad0 + ST_AL);
            LDM4(ah1, ad1 + ST_AH);
            LDM4(al1, ad1 + ST_AL);
            // P1: qh*ch (4 distinct accs)
            MMAI8(acc1[m0][0], ah0, bh[0], bh[1]);
            MMAI8(acc1[m0][1], ah0, bh[2], bh[3]);
            MMAI8(acc1[m1][0], ah1, bh[0], bh[1]);
            MMAI8(acc1[m1][1], ah1, bh[2], bh[3]);
            // P2: qh*cl (4 distinct accs)
            MMAI8(acc2[m0][0], ah0, bl[0], bl[1]);
            MMAI8(acc2[m0][1], ah0, bl[2], bl[3]);
            MMAI8(acc2[m1][0], ah1, bl[0], bl[1]);
            MMAI8(acc2[m1][1], ah1, bl[2], bl[3]);
            // P3: ql*ch — reuses acc2 with gap of 4 mmas (>= mma latency)
            MMAI8(acc2[m0][0], al0, bh[0], bh[1]);
            MMAI8(acc2[m0][1], al0, bh[2], bh[3]);
            MMAI8(acc2[m1][0], al1, bh[0], bh[1]);
            MMAI8(acc2[m1][1], al1, bh[2], bh[3]);
        }
    }

    // ---- epilogue: per-row top2 over this CTA's 64 cols ----
    const int tig = lane & 3;
    const int colBase = ct * BN + wc * 16 + tig * 2;
    float sb2[2][2], hc[2][2];
    #pragma unroll
    for (int f = 0; f < 2; ++f) {
        sb2[f][0] = __ldg(&g_sB[colBase + f * 8]);
        sb2[f][1] = __ldg(&g_sB[colBase + f * 8 + 1]);
        hc[f][0]  = __ldg(&g_halfcsq[colBase + f * 8]);
        hc[f][1]  = __ldg(&g_halfcsq[colBase + f * 8 + 1]);
    }
    unsigned long long* ep = (unsigned long long*)smem;  // [4][128][2] = 8KB
    #pragma unroll
    for (int m = 0; m < 4; ++m) {
        #pragma unroll
        for (int rv = 0; rv < 2; ++rv) {
            const int rowL = wr * 64 + m * 16 + (lane >> 2) + rv * 8;
            const float sa = __ldg(&g_sA[rt * BM + rowL]);
            unsigned long long b1 = 0ull, b2 = 0ull;
            #pragma unroll
            for (int f = 0; f < 2; ++f)
                #pragma unroll
                for (int q = 0; q < 2; ++q) {
                    float v = (float)acc1[m][f][2 * rv + q] +
                              (float)acc2[m][f][2 * rv + q] * (1.0f / 128.0f);
                    float s = sa * sb2[f][q] * v - hc[f][q];
                    top2merge(b1, b2, packSI(s, colBase + f * 8 + q), 0ull);
                }
            #pragma unroll
            for (int o = 1; o < 4; o <<= 1) {
                unsigned long long o1 = __shfl_xor_sync(0xffffffffu, b1, o);
                unsigned long long o2 = __shfl_xor_sync(0xffffffffu, b2, o);
                top2merge(b1, b2, o1, o2);
            }
            if (tig == 0) {
                ep[(wc * 128 + rowL) * 2 + 0] = b1;
                ep[(wc * 128 + rowL) * 2 + 1] = b2;
            }
        }
    }
    __syncthreads();
    if (tid < 128) {
        const int rowL = tid;
        unsigned long long b1 = ep[rowL * 2 + 0];
        unsigned long long b2 = ep[rowL * 2 + 1];
        #pragma unroll
        for (int w = 1; w < 4; ++w)
            top2merge(b1, b2, ep[(w * 128 + rowL) * 2 + 0], ep[(w * 128 + rowL) * 2 + 1]);
        const size_t base = ((size_t)(rt * BM + rowL) * NGRP + ct) * 2;
        g_cand[base]     = b1;
        g_cand[base + 1] = b2;
    }
}

// ---------------- reduce (warp per row) --------------------------------------
__global__ void k_reduce() {
    const int lane = threadIdx.x & 31;
    const int row  = blockIdx.x * 8 + (threadIdx.x >> 5);
    if (row >= NROWS) return;
    const unsigned long long* c = g_cand + (size_t)row * NGRP * 2;
    unsigned long long b1 = 0ull, b2 = 0ull;
    #pragma unroll
    for (int k = 0; k < 4; ++k) {
        unsigned long long v = c[lane + 32 * k];
        top2merge(b1, b2, v, 0ull);
    }
    #pragma unroll
    for (int o = 16; o > 0; o >>= 1) {
        unsigned long long o1 = __shfl_xor_sync(0xffffffffu, b1, o);
        unsigned long long o2 = __shfl_xor_sync(0xffffffffu, b2, o);
        top2merge(b1, b2, o1, o2);
    }
    if (lane == 0) {
        g_idx[row] = (int)(0xFFFFFFFFu - (unsigned)(b1 & 0xFFFFFFFFull));
        float s1 = sortable2f((unsigned)(b1 >> 32));
        float s2 = sortable2f((unsigned)(b2 >> 32));
        if (s1 - s2 < THRESH) {
            int slot = atomicAdd(&g_flag_count, 1);
            if (slot < NROWS) g_flag_list[slot] = row;
        }
    }
}

// ---------------- rescue: exact fp32 re-rank of candidate set ----------------
#define CLIST_MAX 128
__global__ void __launch_bounds__(256)
k_rescue(const float* __restrict__ A, const float* __restrict__ B) {
    __shared__ float xrow[D];
    __shared__ unsigned long long sbest;
    __shared__ int clist[CLIST_MAX];
    __shared__ int ccount;
    const int tid = threadIdx.x, wid = tid >> 5, lid = tid & 31;
    const int count = min(g_flag_count, NROWS);
    for (int i = blockIdx.x; i < count; i += gridDim.x) {
        const int row = g_flag_list[i];
        __syncthreads();
        if (tid == 0) { sbest = 0ull; ccount = 0; }
        for (int j = tid; j < D; j += 256) xrow[j] = A[(size_t)row * D + j];
        __syncthreads();
        const unsigned long long* c = g_cand + (size_t)row * NGRP * 2;
        unsigned long long amax = 0ull;
        for (int e = tid; e < NGRP * 2; e += 256) {
            unsigned long long v = c[e];
            if (v > amax) amax = v;
        }
        atomicMax(&sbest, amax);
        __syncthreads();
        const unsigned thrU = f2sortable(sortable2f((unsigned)(sbest >> 32)) - THRESH);
        for (int e = tid; e < NGRP * 2; e += 256) {
            unsigned long long v = c[e];
            if ((unsigned)(v >> 32) >= thrU) {
                int slot = atomicAdd(&ccount, 1);
                if (slot < CLIST_MAX)
                    clist[slot] = (int)(0xFFFFFFFFu - (unsigned)(v & 0xFFFFFFFFull));
            }
        }
        __syncthreads();
        if (tid == 0) sbest = 0ull;
        __syncthreads();
        const int nc = min(ccount, CLIST_MAX);
        for (int k = wid; k < nc; k += 8) {
            const int m = clist[k];
            const float* cp = B + (size_t)m * D;
            float s = 0.f;
            #pragma unroll
            for (int t = 0; t < 4; ++t) {
                float4 cv = *(const float4*)(cp + t * 128 + lid * 4);
                float4 xv = *(const float4*)(xrow + t * 128 + lid * 4);
                s += cv.x * xv.x + cv.y * xv.y + cv.z * xv.z + cv.w * xv.w;
            }
            #pragma unroll
            for (int o = 16; o > 0; o >>= 1) s += __shfl_xor_sync(0xffffffffu, s, o);
            if (lid == 0) atomicMax(&sbest, packSI(s - __ldg(&g_halfcsq[m]), m));
        }
        __syncthreads();
        if (tid == 0)
            g_idx[row] = (int)(0xFFFFFFFFu - (unsigned)(sbest & 0xFFFFFFFFull));
    }
}

__global__ void k_gather(const float* __restrict__ cb, float* __restrict__ out,
                         float* __restrict__ idx_out) {
    int n = blockIdx.x;
    int idx = g_idx[n];
    const float4* src = (const float4*)(cb + (size_t)idx * D);
    float4* dst = (float4*)(out + (size_t)n * D);
    dst[threadIdx.x] = src[threadIdx.x];
    if (threadIdx.x == 0 && idx_out) idx_out[n] = (float)idx;
}

// ---------------- launch ----------------------------------------------------
extern "C" void kernel_launch(void* const* d_in, const int* in_sizes, int n_in,
                              void* d_out, int out_size) {
    const float* emb = (const float*)d_in[0];   // [65536, 512] f32
    const float* cb  = (const float*)d_in[1];   // [4096, 512]  f32
    float* out = (float*)d_out;

    float* idx_out = nullptr;
    long long need = (long long)NROWS * D + NROWS;
    if ((long long)out_size >= need) idx_out = out + (size_t)NROWS * D;

    cudaFuncSetAttribute(k_gemm, cudaFuncAttributeMaxDynamicSharedMemorySize, SMEM_TOTAL);

    k_init<<<1, 32>>>();
    k_quant_a<<<NROWS / 8, 256>>>(emb);
    k_quant_b<<<MCODES / 8, 256>>>(cb);

    dim3 grid(NT_C, NT_R);                      // (64, 512), ct fastest
    k_gemm<<<grid, 256, SMEM_TOTAL>>>();

    k_reduce<<<NROWS / 8, 256>>>();
    k_rescue<<<512, 256>>>(emb, cb);
    k_gather<<<NROWS, 128>>>(cb, out, idx_out);
}

// round 10
// speedup vs baseline: 1.2271x; 1.2271x over previous
#include <cuda_runtime.h>
#include <cstdint>

#define D        512
#define NROWS    65536
#define MCODES   4096
#define BM       128
#define BN       64
#define BK       32
#define NKC      (D / BK)        // 16
#define NT_R     (NROWS / BM)    // 512
#define NT_C     (MCODES / BN)   // 64
#define NGRP     NT_C            // one 64-col group per ct
#define THRESH   0.05f

// ---------------- scratch (device globals) -----------------------------------
#define A_BLK 4096               // 128 rows x 32 int8 per (rt,kc)
#define B_BLK 2048               // 64 rows x 32 int8 per (ct,kc)
__device__ __align__(128) unsigned char qAh[(size_t)NT_R * NKC * A_BLK]; // 32MB
__device__ __align__(128) unsigned char qAl[(size_t)NT_R * NKC * A_BLK]; // 32MB
__device__ __align__(128) unsigned char qBh[(size_t)NT_C * NKC * B_BLK]; // 2MB
__device__ __align__(128) unsigned char qBl[(size_t)NT_C * NKC * B_BLK]; // 2MB

__device__ float              g_sA[NROWS];
__device__ float              g_sB[MCODES];
__device__ float              g_halfcsq[MCODES];
__device__ unsigned long long g_cand[(size_t)NROWS * NGRP * 2];  // 67MB
__device__ int                g_idx[NROWS];
__device__ int                g_flag_count;
__device__ int                g_flag_list[NROWS];

// ---------------- helpers ----------------------------------------------------
__device__ __forceinline__ unsigned int f2sortable(float f) {
    unsigned int u = __float_as_uint(f);
    return (u & 0x80000000u) ? ~u : (u | 0x80000000u);
}
__device__ __forceinline__ float sortable2f(unsigned int u) {
    unsigned int b = (u & 0x80000000u) ? (u ^ 0x80000000u) : ~u;
    return __uint_as_float(b);
}
__device__ __forceinline__ unsigned long long packSI(float s, int col) {
    return ((unsigned long long)f2sortable(s) << 32) |
           (unsigned long long)(0xFFFFFFFFu - (unsigned)col);
}
__device__ __forceinline__ void top2merge(unsigned long long& b1, unsigned long long& b2,
                                          unsigned long long o1, unsigned long long o2) {
    if (o1 > b1) { b2 = (b1 > o2) ? b1 : o2; b1 = o1; }
    else if (o1 > b2) { b2 = o1; }
}
__device__ __forceinline__ uint32_t smem_u32(const void* p) {
    uint32_t a;
    asm("{ .reg .u64 t; cvta.to.shared.u64 t, %1; cvt.u32.u64 %0, t; }" : "=r"(a) : "l"(p));
    return a;
}

// ---------------- cp.async / ldmatrix / mma ----------------------------------
__device__ __forceinline__ void cp16(uint32_t dst, const void* src) {
    asm volatile("cp.async.cg.shared.global [%0], [%1], 16;" :: "r"(dst), "l"(src) : "memory");
}
#define CP_COMMIT() asm volatile("cp.async.commit_group;" ::: "memory")
#define CP_WAIT(N)  asm volatile("cp.async.wait_group %0;" :: "n"(N) : "memory")

#define LDM4(r, addr) \
    asm volatile("ldmatrix.sync.aligned.m8n8.x4.shared.b16 {%0,%1,%2,%3}, [%4];" \
        : "=r"((r)[0]), "=r"((r)[1]), "=r"((r)[2]), "=r"((r)[3]) : "r"(addr))

#define MMAI8(d, a, b0_, b1_) \
    asm volatile("mma.sync.aligned.m16n8k32.row.col.s32.s8.s8.s32 " \
        "{%0,%1,%2,%3},{%4,%5,%6,%7},{%8,%9},{%0,%1,%2,%3};" \
        : "+r"((d)[0]), "+r"((d)[1]), "+r"((d)[2]), "+r"((d)[3]) \
        : "r"((a)[0]), "r"((a)[1]), "r"((a)[2]), "r"((a)[3]), "r"(b0_), "r"(b1_))

// ---------------- stage layout -----------------------------------------------
#define ST_AH 0
#define ST_AL 4096
#define ST_BH 8192
#define ST_BL 10240
#define STG   12288
#define NSTAGE 4
#define SMEM_TOTAL (NSTAGE * STG)   // 49152

// ---------------- quantization (unchanged layouts) ----------------------------
__device__ __forceinline__ uint32_t pack4(int q0, int q1, int q2, int q3) {
    return (uint32_t)(q0 & 0xFF) | ((uint32_t)(q1 & 0xFF) << 8) |
           ((uint32_t)(q2 & 0xFF) << 16) | ((uint32_t)(q3 & 0xFF) << 24);
}

template<int RSHIFT, int BLKSZ>
__device__ __forceinline__ void quant_row(const float* __restrict__ X, int row,
                                          unsigned char* __restrict__ ph,
                                          unsigned char* __restrict__ pl,
                                          float* __restrict__ scale_out,
                                          float* __restrict__ halfcsq_out) {
    const int lane = threadIdx.x & 31;
    const float4* xp = (const float4*)(X + (size_t)row * D + lane * 16);
    float4 v[4];
    float amax = 0.f, ssq = 0.f;
    #pragma unroll
    for (int i = 0; i < 4; ++i) {
        v[i] = xp[i];
        amax = fmaxf(amax, fmaxf(fmaxf(fabsf(v[i].x), fabsf(v[i].y)),
                                 fmaxf(fabsf(v[i].z), fabsf(v[i].w))));
        if (halfcsq_out)
            ssq += v[i].x * v[i].x + v[i].y * v[i].y + v[i].z * v[i].z + v[i].w * v[i].w;
    }
    #pragma unroll
    for (int o = 16; o > 0; o >>= 1) {
        amax = fmaxf(amax, __shfl_xor_sync(0xffffffffu, amax, o));
        if (halfcsq_out) ssq += __shfl_xor_sync(0xffffffffu, ssq, o);
    }
    amax = fmaxf(amax, 1e-30f);
    const float inv = 127.f / amax;
    uint32_t H[4], L[4];
    #pragma unroll
    for (int i = 0; i < 4; ++i) {
        float f[4] = {v[i].x, v[i].y, v[i].z, v[i].w};
        int qh[4], ql[4];
        #pragma unroll
        for (int j = 0; j < 4; ++j) {
            float t = f[j] * inv;
            qh[j] = __float2int_rn(t);
            qh[j] = max(-127, min(127, qh[j]));
            float rh = t - (float)qh[j];
            ql[j] = __float2int_rn(rh * 128.f);
        }
        H[i] = pack4(qh[0], qh[1], qh[2], qh[3]);
        L[i] = pack4(ql[0], ql[1], ql[2], ql[3]);
    }
    const int rt  = row >> RSHIFT;
    const int rIn = row & ((1 << RSHIFT) - 1);
    const int kc  = lane >> 1;
    const int c   = lane & 1;
    const size_t off = (size_t)(rt * NKC + kc) * BLKSZ +
                       (size_t)(c * (1 << RSHIFT) + rIn) * 16;
    *(uint4*)(ph + off) = make_uint4(H[0], H[1], H[2], H[3]);
    *(uint4*)(pl + off) = make_uint4(L[0], L[1], L[2], L[3]);
    if (lane == 0) {
        scale_out[row] = amax / 127.f;
        if (halfcsq_out) halfcsq_out[row] = 0.5f * ssq;
    }
}

__global__ void k_quant_a(const float* __restrict__ A) {
    int row = blockIdx.x * 8 + (threadIdx.x >> 5);
    if (row < NROWS) quant_row<7, A_BLK>(A, row, qAh, qAl, g_sA, nullptr);
}
__global__ void k_quant_b(const float* __restrict__ B) {
    int row = blockIdx.x * 8 + (threadIdx.x >> 5);
    if (row < MCODES) quant_row<6, B_BLK>(B, row, qBh, qBl, g_sB, g_halfcsq);
}

__global__ void k_init() { if (threadIdx.x == 0) g_flag_count = 0; }

// ---------------- main GEMM: int8 double-digit, 3 products -------------------
// 128 thr (4 warps, 2x2), warp tile 64 rows x 32 cols. 2 CTAs/SM.
// smem-traffic per mma: 192B (vs 277B in the 8-warp/16-col version).
__global__ void __launch_bounds__(128, 2)
k_gemm() {
    extern __shared__ char smem[];
    const uint32_t sb = smem_u32(smem);
    const int tid  = threadIdx.x;
    const int wid  = tid >> 5;
    const int lane = tid & 31;
    const int ct = blockIdx.x;           // 0..63 fastest -> B fully L2-resident
    const int rt = blockIdx.y;           // 0..511
    const int wr = wid >> 1;             // 0..1 -> rows wr*64..+63
    const int wc = wid & 1;              // 0..1 -> cols wc*32..+31

    const unsigned char* aH = qAh + (size_t)(rt * NKC) * A_BLK;
    const unsigned char* aL = qAl + (size_t)(rt * NKC) * A_BLK;
    const unsigned char* bH = qBh + (size_t)(ct * NKC) * B_BLK;
    const unsigned char* bL = qBl + (size_t)(ct * NKC) * B_BLK;

    auto load_stage = [&](int kc) {
        const uint32_t st = sb + (kc & (NSTAGE - 1)) * STG;
        const uint32_t o = tid * 16;               // 0..2047
        const unsigned char* pa_h = aH + (size_t)kc * A_BLK;
        const unsigned char* pa_l = aL + (size_t)kc * A_BLK;
        cp16(st + ST_AH + o,        pa_h + o);
        cp16(st + ST_AH + o + 2048, pa_h + o + 2048);
        cp16(st + ST_AL + o,        pa_l + o);
        cp16(st + ST_AL + o + 2048, pa_l + o + 2048);
        cp16(st + ST_BH + o, bH + (size_t)kc * B_BLK + o);
        cp16(st + ST_BL + o, bL + (size_t)kc * B_BLK + o);
    };

    // ldmatrix lane address pieces (same fragment mapping as validated rounds)
    const int mtx = lane >> 3;
    const uint32_t aOff = (uint32_t)((mtx >> 1) * 2048 +
                          (wr * 64 + (mtx & 1) * 8 + (lane & 7)) * 16);
    const uint32_t bOff = (uint32_t)((mtx & 1) * 1024 +
                          (wc * 32 + (mtx >> 1) * 8 + (lane & 7)) * 16);

    int acc1[4][4][4], acc2[4][4][4];
    #pragma unroll
    for (int m = 0; m < 4; ++m)
        #pragma unroll
        for (int n = 0; n < 4; ++n)
            #pragma unroll
            for (int q = 0; q < 4; ++q) { acc1[m][n][q] = 0; acc2[m][n][q] = 0; }

    load_stage(0); CP_COMMIT();
    load_stage(1); CP_COMMIT();
    load_stage(2); CP_COMMIT();

    #pragma unroll 1
    for (int kc = 0; kc < NKC; ++kc) {
        if (kc < NKC - 2)       { CP_WAIT(2); }
        else if (kc == NKC - 2) { CP_WAIT(1); }
        else                    { CP_WAIT(0); }
        __syncthreads();
        if (kc + 3 < NKC) { load_stage(kc + 3); CP_COMMIT(); }

        const uint32_t st = sb + (kc & (NSTAGE - 1)) * STG;
        uint32_t bh0[4], bh1[4], bl0[4], bl1[4];
        LDM4(bh0, st + ST_BH + bOff);
        LDM4(bh1, st + ST_BH + bOff + 256);        // +16 cols
        LDM4(bl0, st + ST_BL + bOff);
        LDM4(bl1, st + ST_BL + bOff + 256);
        #pragma unroll
        for (int m = 0; m < 4; ++m) {
            uint32_t ah[4], al[4];
            const uint32_t ad = st + aOff + (uint32_t)(m * 256);
            LDM4(ah, ad + ST_AH);
            LDM4(al, ad + ST_AL);
            // P1: qh*ch -> acc1 (4 distinct accs)
            MMAI8(acc1[m][0], ah, bh0[0], bh0[1]);
            MMAI8(acc1[m][1], ah, bh0[2], bh0[3]);
            MMAI8(acc1[m][2], ah, bh1[0], bh1[1]);
            MMAI8(acc1[m][3], ah, bh1[2], bh1[3]);
            // P2: qh*cl -> acc2
            MMAI8(acc2[m][0], ah, bl0[0], bl0[1]);
            MMAI8(acc2[m][1], ah, bl0[2], bl0[3]);
            MMAI8(acc2[m][2], ah, bl1[0], bl1[1]);
            MMAI8(acc2[m][3], ah, bl1[2], bl1[3]);
            // P3: ql*ch -> acc2 (reuse gap = 4 mmas)
            MMAI8(acc2[m][0], al, bh0[0], bh0[1]);
            MMAI8(acc2[m][1], al, bh0[2], bh0[3]);
            MMAI8(acc2[m][2], al, bh1[0], bh1[1]);
            MMAI8(acc2[m][3], al, bh1[2], bh1[3]);
        }
    }

    // ---- epilogue: per-row top2 over this CTA's 64 cols ----
    const int tig = lane & 3;
    const int colBase = ct * BN + wc * 32 + tig * 2;
    float sb2[4][2], hc[4][2];
    #pragma unroll
    for (int nf = 0; nf < 4; ++nf) {
        sb2[nf][0] = __ldg(&g_sB[colBase + nf * 8]);
        sb2[nf][1] = __ldg(&g_sB[colBase + nf * 8 + 1]);
        hc[nf][0]  = __ldg(&g_halfcsq[colBase + nf * 8]);
        hc[nf][1]  = __ldg(&g_halfcsq[colBase + nf * 8 + 1]);
    }
    unsigned long long* ep = (unsigned long long*)smem;  // [2][128][2] = 4KB
    #pragma unroll
    for (int m = 0; m < 4; ++m) {
        #pragma unroll
        for (int rv = 0; rv < 2; ++rv) {
            const int rowL = wr * 64 + m * 16 + (lane >> 2) + rv * 8;
            const float sa = __ldg(&g_sA[rt * BM + rowL]);
            unsigned long long b1 = 0ull, b2 = 0ull;
            #pragma unroll
            for (int nf = 0; nf < 4; ++nf)
                #pragma unroll
                for (int q = 0; q < 2; ++q) {
                    float v = (float)acc1[m][nf][2 * rv + q] +
                              (float)acc2[m][nf][2 * rv + q] * (1.0f / 128.0f);
                    float s = sa * sb2[nf][q] * v - hc[nf][q];
                    top2merge(b1, b2, packSI(s, colBase + nf * 8 + q), 0ull);
                }
            #pragma unroll
            for (int o = 1; o < 4; o <<= 1) {
                unsigned long long o1 = __shfl_xor_sync(0xffffffffu, b1, o);
                unsigned long long o2 = __shfl_xor_sync(0xffffffffu, b2, o);
                top2merge(b1, b2, o1, o2);
            }
            if (tig == 0) {
                ep[(wc * 128 + rowL) * 2 + 0] = b1;
                ep[(wc * 128 + rowL) * 2 + 1] = b2;
            }
        }
    }
    __syncthreads();
    {
        const int rowL = tid;                  // 128 rows, 128 threads
        unsigned long long b1 = ep[rowL * 2 + 0];
        unsigned long long b2 = ep[rowL * 2 + 1];
        top2merge(b1, b2, ep[(128 + rowL) * 2 + 0], ep[(128 + rowL) * 2 + 1]);
        const size_t base = ((size_t)(rt * BM + rowL) * NGRP + ct) * 2;
        g_cand[base]     = b1;
        g_cand[base + 1] = b2;
    }
}

// ---------------- reduce (warp per row) --------------------------------------
__global__ void k_reduce() {
    const int lane = threadIdx.x & 31;
    const int row  = blockIdx.x * 8 + (threadIdx.x >> 5);
    if (row >= NROWS) return;
    const unsigned long long* c = g_cand + (size_t)row * NGRP * 2;
    unsigned long long b1 = 0ull, b2 = 0ull;
    #pragma unroll
    for (int k = 0; k < 4; ++k) {
        unsigned long long v = c[lane + 32 * k];
        top2merge(b1, b2, v, 0ull);
    }
    #pragma unroll
    for (int o = 16; o > 0; o >>= 1) {
        unsigned long long o1 = __shfl_xor_sync(0xffffffffu, b1, o);
        unsigned long long o2 = __shfl_xor_sync(0xffffffffu, b2, o);
        top2merge(b1, b2, o1, o2);
    }
    if (lane == 0) {
        g_idx[row] = (int)(0xFFFFFFFFu - (unsigned)(b1 & 0xFFFFFFFFull));
        float s1 = sortable2f((unsigned)(b1 >> 32));
        float s2 = sortable2f((unsigned)(b2 >> 32));
        if (s1 - s2 < THRESH) {
            int slot = atomicAdd(&g_flag_count, 1);
            if (slot < NROWS) g_flag_list[slot] = row;
        }
    }
}

// ---------------- rescue: exact fp32 re-rank of candidate set ----------------
#define CLIST_MAX 128
__global__ void __launch_bounds__(256)
k_rescue(const float* __restrict__ A, const float* __restrict__ B) {
    __shared__ float xrow[D];
    __shared__ unsigned long long sbest;
    __shared__ int clist[CLIST_MAX];
    __shared__ int ccount;
    const int tid = threadIdx.x, wid = tid >> 5, lid = tid & 31;
    const int count = min(g_flag_count, NROWS);
    for (int i = blockIdx.x; i < count; i += gridDim.x) {
        const int row = g_flag_list[i];
        __syncthreads();
        if (tid == 0) { sbest = 0ull; ccount = 0; }
        for (int j = tid; j < D; j += 256) xrow[j] = A[(size_t)row * D + j];
        __syncthreads();
        const unsigned long long* c = g_cand + (size_t)row * NGRP * 2;
        unsigned long long amax = 0ull;
        for (int e = tid; e < NGRP * 2; e += 256) {
            unsigned long long v = c[e];
            if (v > amax) amax = v;
        }
        atomicMax(&sbest, amax);
        __syncthreads();
        const unsigned thrU = f2sortable(sortable2f((unsigned)(sbest >> 32)) - THRESH);
        for (int e = tid; e < NGRP * 2; e += 256) {
            unsigned long long v = c[e];
            if ((unsigned)(v >> 32) >= thrU) {
                int slot = atomicAdd(&ccount, 1);
                if (slot < CLIST_MAX)
                    clist[slot] = (int)(0xFFFFFFFFu - (unsigned)(v & 0xFFFFFFFFull));
            }
        }
        __syncthreads();
        if (tid == 0) sbest = 0ull;
        __syncthreads();
        const int nc = min(ccount, CLIST_MAX);
        for (int k = wid; k < nc; k += 8) {
            const int m = clist[k];
            const float* cp = B + (size_t)m * D;
            float s = 0.f;
            #pragma unroll
            for (int t = 0; t < 4; ++t) {
                float4 cv = *(const float4*)(cp + t * 128 + lid * 4);
                float4 xv = *(const float4*)(xrow + t * 128 + lid * 4);
                s += cv.x * xv.x + cv.y * xv.y + cv.z * xv.z + cv.w * xv.w;
            }
            #pragma unroll
            for (int o = 16; o > 0; o >>= 1) s += __shfl_xor_sync(0xffffffffu, s, o);
            if (lid == 0) atomicMax(&sbest, packSI(s - __ldg(&g_halfcsq[m]), m));
        }
        __syncthreads();
        if (tid == 0)
            g_idx[row] = (int)(0xFFFFFFFFu - (unsigned)(sbest & 0xFFFFFFFFull));
    }
}

__global__ void k_gather(const float* __restrict__ cb, float* __restrict__ out,
                         float* __restrict__ idx_out) {
    int n = blockIdx.x;
    int idx = g_idx[n];
    const float4* src = (const float4*)(cb + (size_t)idx * D);
    float4* dst = (float4*)(out + (size_t)n * D);
    dst[threadIdx.x] = src[threadIdx.x];
    if (threadIdx.x == 0 && idx_out) idx_out[n] = (float)idx;
}

// ---------------- launch ----------------------------------------------------
extern "C" void kernel_launch(void* const* d_in, const int* in_sizes, int n_in,
                              void* d_out, int out_size) {
    const float* emb = (const float*)d_in[0];   // [65536, 512] f32
    const float* cb  = (const float*)d_in[1];   // [4096, 512]  f32
    float* out = (float*)d_out;

    float* idx_out = nullptr;
    long long need = (long long)NROWS * D + NROWS;
    if ((long long)out_size >= need) idx_out = out + (size_t)NROWS * D;

    cudaFuncSetAttribute(k_gemm, cudaFuncAttributeMaxDynamicSharedMemorySize, SMEM_TOTAL);

    k_init<<<1, 32>>>();
    k_quant_a<<<NROWS / 8, 256>>>(emb);
    k_quant_b<<<MCODES / 8, 256>>>(cb);

    dim3 grid(NT_C, NT_R);                      // (64, 512), ct fastest
    k_gemm<<<grid, 128, SMEM_TOTAL>>>();

    k_reduce<<<NROWS / 8, 256>>>();
    k_rescue<<<512, 256>>>(emb, cb);
    k_gather<<<NROWS, 128>>>(cb, out, idx_out);
}

// round 12
// speedup vs baseline: 2.0284x; 1.6530x over previous
#include <cuda_runtime.h>
#include <cstdint>

#define D        512
#define NROWS    65536
#define MCODES   4096
#define BM       128
#define BN       128
#define BK       32
#define NKC      16
#define NT_R     512
#define NT_C     32
#define NGRP     64              // 64-col groups per row
#define THRESH   2.5f

// ---------------- scratch (device globals) -----------------------------------
#define A_BLK 4096               // 128 rows x 32 int8 per (rt,kc)
#define B_BLK 4096               // 128 rows x 32 int8 per (ct,kc)
__device__ __align__(128) unsigned char qA[(size_t)NT_R * NKC * A_BLK]; // 32MB
__device__ __align__(128) unsigned char qB[(size_t)NT_C * NKC * B_BLK]; // 2MB

__device__ float              g_sA[NROWS];
__device__ float              g_sB[MCODES];
__device__ float              g_halfcsq[MCODES];
__device__ unsigned long long g_cand[(size_t)NROWS * NGRP * 2];  // 67MB
__device__ int                g_idx[NROWS];
__device__ int                g_flag_count;
__device__ int                g_flag_list[NROWS];

// ---------------- helpers ----------------------------------------------------
__device__ __forceinline__ unsigned int f2sortable(float f) {
    unsigned int u = __float_as_uint(f);
    return (u & 0x80000000u) ? ~u : (u | 0x80000000u);
}
__device__ __forceinline__ float sortable2f(unsigned int u) {
    unsigned int b = (u & 0x80000000u) ? (u ^ 0x80000000u) : ~u;
    return __uint_as_float(b);
}
__device__ __forceinline__ unsigned long long packSI(float s, int col) {
    return ((unsigned long long)f2sortable(s) << 32) |
           (unsigned long long)(0xFFFFFFFFu - (unsigned)col);
}
__device__ __forceinline__ void top2merge(unsigned long long& b1, unsigned long long& b2,
                                          unsigned long long o1, unsigned long long o2) {
    if (o1 > b1) { b2 = (b1 > o2) ? b1 : o2; b1 = o1; }
    else if (o1 > b2) { b2 = o1; }
}
__device__ __forceinline__ uint32_t smem_u32(const void* p) {
    uint32_t a;
    asm("{ .reg .u64 t; cvta.to.shared.u64 t, %1; cvt.u32.u64 %0, t; }" : "=r"(a) : "l"(p));
    return a;
}

// ---------------- cp.async / ldmatrix / mma ----------------------------------
__device__ __forceinline__ void cp16(uint32_t dst, const void* src) {
    asm volatile("cp.async.cg.shared.global [%0], [%1], 16;" :: "r"(dst), "l"(src) : "memory");
}
#define CP_COMMIT() asm volatile("cp.async.commit_group;" ::: "memory")
#define CP_WAIT(N)  asm volatile("cp.async.wait_group %0;" :: "n"(N) : "memory")

#define LDM4(r, addr) \
    asm volatile("ldmatrix.sync.aligned.m8n8.x4.shared.b16 {%0,%1,%2,%3}, [%4];" \
        : "=r"((r)[0]), "=r"((r)[1]), "=r"((r)[2]), "=r"((r)[3]) : "r"(addr))

#define MMAI8(d, a, b0_, b1_) \
    asm volatile("mma.sync.aligned.m16n8k32.row.col.s32.s8.s8.s32 " \
        "{%0,%1,%2,%3},{%4,%5,%6,%7},{%8,%9},{%0,%1,%2,%3};" \
        : "+r"((d)[0]), "+r"((d)[1]), "+r"((d)[2]), "+r"((d)[3]) \
        : "r"((a)[0]), "r"((a)[1]), "r"((a)[2]), "r"((a)[3]), "r"(b0_), "r"(b1_))

// ---------------- stage layout -----------------------------------------------
#define STG    8192              // A 4KB + B 4KB
#define NSTAGE 4
#define SMEM_TOTAL (NSTAGE * STG)   // 32768

// ---------------- quantization (single digit) --------------------------------
__device__ __forceinline__ uint32_t pack4(int q0, int q1, int q2, int q3) {
    return (uint32_t)(q0 & 0xFF) | ((uint32_t)(q1 & 0xFF) << 8) |
           ((uint32_t)(q2 & 0xFF) << 16) | ((uint32_t)(q3 & 0xFF) << 24);
}

__device__ __forceinline__ void quant_row(const float* __restrict__ X, int row,
                                          unsigned char* __restrict__ pq,
                                          float* __restrict__ scale_out,
                                          float* __restrict__ halfcsq_out) {
    const int lane = threadIdx.x & 31;
    const float4* xp = (const float4*)(X + (size_t)row * D + lane * 16);
    float4 v[4];
    float amax = 0.f, ssq = 0.f;
    #pragma unroll
    for (int i = 0; i < 4; ++i) {
        v[i] = xp[i];
        amax = fmaxf(amax, fmaxf(fmaxf(fabsf(v[i].x), fabsf(v[i].y)),
                                 fmaxf(fabsf(v[i].z), fabsf(v[i].w))));
        if (halfcsq_out)
            ssq += v[i].x * v[i].x + v[i].y * v[i].y + v[i].z * v[i].z + v[i].w * v[i].w;
    }
    #pragma unroll
    for (int o = 16; o > 0; o >>= 1) {
        amax = fmaxf(amax, __shfl_xor_sync(0xffffffffu, amax, o));
        if (halfcsq_out) ssq += __shfl_xor_sync(0xffffffffu, ssq, o);
    }
    amax = fmaxf(amax, 1e-30f);
    const float inv = 127.f / amax;
    uint32_t H[4];
    #pragma unroll
    for (int i = 0; i < 4; ++i) {
        float f[4] = {v[i].x, v[i].y, v[i].z, v[i].w};
        int qh[4];
        #pragma unroll
        for (int j = 0; j < 4; ++j) {
            qh[j] = __float2int_rn(f[j] * inv);
            qh[j] = max(-127, min(127, qh[j]));
        }
        H[i] = pack4(qh[0], qh[1], qh[2], qh[3]);
    }
    const int rt  = row >> 7;
    const int rIn = row & 127;
    const int kc  = lane >> 1;
    const int c   = lane & 1;
    const size_t off = (size_t)(rt * NKC + kc) * 4096 + (size_t)(c * 128 + rIn) * 16;
    *(uint4*)(pq + off) = make_uint4(H[0], H[1], H[2], H[3]);
    if (lane == 0) {
        scale_out[row] = amax / 127.f;
        if (halfcsq_out) halfcsq_out[row] = 0.5f * ssq;
    }
}

__global__ void k_quant_a(const float* __restrict__ A) {
    int row = blockIdx.x * 8 + (threadIdx.x >> 5);
    if (row < NROWS) quant_row(A, row, qA, g_sA, nullptr);
}
__global__ void k_quant_b(const float* __restrict__ B) {
    int row = blockIdx.x * 8 + (threadIdx.x >> 5);
    if (row < MCODES) quant_row(B, row, qB, g_sB, g_halfcsq);
}

__global__ void k_init() { if (threadIdx.x == 0) g_flag_count = 0; }

// ---------------- main GEMM: single-product int8, frag prefetch --------------
// 128 thr (4 warps, 2x2), warp tile 64x64, CTA 128x128, 2 CTAs/SM.
__global__ void __launch_bounds__(128, 2)
k_gemm() {
    extern __shared__ char smem[];
    const uint32_t sb = smem_u32(smem);
    const int tid  = threadIdx.x;
    const int wid  = tid >> 5;
    const int lane = tid & 31;
    const int ct = blockIdx.x;           // 0..31 fastest -> B fully L2-resident
    const int rt = blockIdx.y;           // 0..511
    const int wr = wid >> 1;             // 0..1 -> rows wr*64..+63
    const int wc = wid & 1;              // 0..1 -> cols wc*64..+63

    const unsigned char* aP = qA + (size_t)(rt * NKC) * A_BLK;
    const unsigned char* bP = qB + (size_t)(ct * NKC) * B_BLK;

    auto load_stage = [&](int kc) {
        const uint32_t st = sb + (kc & (NSTAGE - 1)) * STG;
        const uint32_t o = tid * 16;               // 0..2047
        const unsigned char* pa = aP + (size_t)kc * A_BLK;
        const unsigned char* pb = bP + (size_t)kc * B_BLK;
        cp16(st + o,        pa + o);
        cp16(st + o + 2048, pa + o + 2048);
        cp16(st + 4096 + o,        pb + o);
        cp16(st + 4096 + o + 2048, pb + o + 2048);
    };

    // ldmatrix lane address pieces (validated fragment mapping)
    const int mtx = lane >> 3;
    const uint32_t aOff = (uint32_t)((mtx >> 1) * 2048 +
                          (wr * 64 + (mtx & 1) * 8 + (lane & 7)) * 16);
    const uint32_t bOff = (uint32_t)(4096 + (mtx & 1) * 2048 +
                          (wc * 64 + (mtx >> 1) * 8 + (lane & 7)) * 16);

    int acc[4][8][4];
    #pragma unroll
    for (int m = 0; m < 4; ++m)
        #pragma unroll
        for (int n = 0; n < 8; ++n)
            #pragma unroll
            for (int q = 0; q < 4; ++q) acc[m][n][q] = 0;

    load_stage(0); CP_COMMIT();
    load_stage(1); CP_COMMIT();
    load_stage(2); CP_COMMIT();

    uint32_t fa[4][4], fb[4][4], ga[4][4], gb[4][4];
    CP_WAIT(2);
    __syncthreads();
    {   // prologue fragments: stage 0
        #pragma unroll
        for (int m = 0; m < 4; ++m) LDM4(fa[m], sb + aOff + (uint32_t)(m * 256));
        #pragma unroll
        for (int j = 0; j < 4; ++j) LDM4(fb[j], sb + bOff + (uint32_t)(j * 256));
    }

    #pragma unroll 1
    for (int kc = 0; kc < NKC; ++kc) {
        if (kc + 3 < NKC) { load_stage(kc + 3); CP_COMMIT(); }
        if (kc + 1 < NKC) {
            if (kc < NKC - 3)       { CP_WAIT(2); }
            else if (kc == NKC - 3) { CP_WAIT(1); }
            else                    { CP_WAIT(0); }
            __syncthreads();
            const uint32_t st = sb + ((kc + 1) & (NSTAGE - 1)) * STG;
            #pragma unroll
            for (int m = 0; m < 4; ++m) LDM4(ga[m], st + aOff + (uint32_t)(m * 256));
            #pragma unroll
            for (int j = 0; j < 4; ++j) LDM4(gb[j], st + bOff + (uint32_t)(j * 256));
        }
        // 32 mmas on current fragments, all-distinct accumulators
        #pragma unroll
        for (int m = 0; m < 4; ++m)
            #pragma unroll
            for (int j = 0; j < 4; ++j) {
                MMAI8(acc[m][2 * j],     fa[m], fb[j][0], fb[j][1]);
                MMAI8(acc[m][2 * j + 1], fa[m], fb[j][2], fb[j][3]);
            }
        if (kc + 1 < NKC) {
            #pragma unroll
            for (int m = 0; m < 4; ++m)
                #pragma unroll
                for (int q = 0; q < 4; ++q) { fa[m][q] = ga[m][q]; fb[m][q] = gb[m][q]; }
        }
    }

    // ---- epilogue: per-row top2 over this warp's 64 cols (= one group) ----
    const int tig = lane & 3;
    const int colBase = ct * BN + wc * 64 + tig * 2;
    float sb2[8][2], hc[8][2];
    #pragma unroll
    for (int nf = 0; nf < 8; ++nf) {
        sb2[nf][0] = __ldg(&g_sB[colBase + nf * 8]);
        sb2[nf][1] = __ldg(&g_sB[colBase + nf * 8 + 1]);
        hc[nf][0]  = __ldg(&g_halfcsq[colBase + nf * 8]);
        hc[nf][1]  = __ldg(&g_halfcsq[colBase + nf * 8 + 1]);
    }
    #pragma unroll
    for (int m = 0; m < 4; ++m) {
        #pragma unroll
        for (int rv = 0; rv < 2; ++rv) {
            const int row = rt * BM + wr * 64 + m * 16 + (lane >> 2) + rv * 8;
            const float sa = __ldg(&g_sA[row]);
            unsigned long long b1 = 0ull, b2 = 0ull;
            #pragma unroll
            for (int nf = 0; nf < 8; ++nf)
                #pragma unroll
                for (int q = 0; q < 2; ++q) {
                    float s = sa * sb2[nf][q] * (float)acc[m][nf][2 * rv + q] - hc[nf][q];
                    top2merge(b1, b2, packSI(s, colBase + nf * 8 + q), 0ull);
                }
            #pragma unroll
            for (int o = 1; o < 4; o <<= 1) {
                unsigned long long o1 = __shfl_xor_sync(0xffffffffu, b1, o);
                unsigned long long o2 = __shfl_xor_sync(0xffffffffu, b2, o);
                top2merge(b1, b2, o1, o2);
            }
            if (tig == 0) {
                const size_t base = ((size_t)row * NGRP + (ct * 2 + wc)) * 2;
                g_cand[base]     = b1;
                g_cand[base + 1] = b2;
            }
        }
    }
}

// ---------------- reduce (warp per row) --------------------------------------
__global__ void k_reduce() {
    const int lane = threadIdx.x & 31;
    const int row  = blockIdx.x * 8 + (threadIdx.x >> 5);
    if (row >= NROWS) return;
    const unsigned long long* c = g_cand + (size_t)row * NGRP * 2;
    unsigned long long b1 = 0ull, b2 = 0ull;
    #pragma unroll
    for (int k = 0; k < 4; ++k) {
        unsigned long long v = c[lane + 32 * k];
        top2merge(b1, b2, v, 0ull);
    }
    #pragma unroll
    for (int o = 16; o > 0; o >>= 1) {
        unsigned long long o1 = __shfl_xor_sync(0xffffffffu, b1, o);
        unsigned long long o2 = __shfl_xor_sync(0xffffffffu, b2, o);
        top2merge(b1, b2, o1, o2);
    }
    if (lane == 0) {
        g_idx[row] = (int)(0xFFFFFFFFu - (unsigned)(b1 & 0xFFFFFFFFull));
        float s1 = sortable2f((unsigned)(b1 >> 32));
        float s2 = sortable2f((unsigned)(b2 >> 32));
        if (s1 - s2 < THRESH) {
            int slot = atomicAdd(&g_flag_count, 1);
            if (slot < NROWS) g_flag_list[slot] = row;
        }
    }
}

// ---------------- rescue: exact fp32 re-rank of candidate set ----------------
#define CLIST_MAX 128
__global__ void __launch_bounds__(256)
k_rescue(const float* __restrict__ A, const float* __restrict__ B) {
    __shared__ float xrow[D];
    __shared__ unsigned long long sbest;
    __shared__ int clist[CLIST_MAX];
    __shared__ int ccount;
    const int tid = threadIdx.x, wid = tid >> 5, lid = tid & 31;
    const int count = min(g_flag_count, NROWS);
    for (int i = blockIdx.x; i < count; i += gridDim.x) {
        const int row = g_flag_list[i];
        __syncthreads();
        if (tid == 0) { sbest = 0ull; ccount = 0; }
        for (int j = tid; j < D; j += 256) xrow[j] = A[(size_t)row * D + j];
        __syncthreads();
        const unsigned long long* c = g_cand + (size_t)row * NGRP * 2;
        unsigned long long amax = 0ull;
        for (int e = tid; e < NGRP * 2; e += 256) {
            unsigned long long v = c[e];
            if (v > amax) amax = v;
        }
        atomicMax(&sbest, amax);
        __syncthreads();
        const unsigned thrU = f2sortable(sortable2f((unsigned)(sbest >> 32)) - THRESH);
        for (int e = tid; e < NGRP * 2; e += 256) {
            unsigned long long v = c[e];
            if ((unsigned)(v >> 32) >= thrU) {
                int slot = atomicAdd(&ccount, 1);
                if (slot < CLIST_MAX)
                    clist[slot] = (int)(0xFFFFFFFFu - (unsigned)(v & 0xFFFFFFFFull));
            }
        }
        __syncthreads();
        if (tid == 0) sbest = 0ull;
        __syncthreads();
        const int nc = min(ccount, CLIST_MAX);
        for (int k = wid; k < nc; k += 8) {
            const int m = clist[k];
            const float* cp = B + (size_t)m * D;
            float s = 0.f;
            #pragma unroll
            for (int t = 0; t < 4; ++t) {
                float4 cv = *(const float4*)(cp + t * 128 + lid * 4);
                float4 xv = *(const float4*)(xrow + t * 128 + lid * 4);
                s += cv.x * xv.x + cv.y * xv.y + cv.z * xv.z + cv.w * xv.w;
            }
            #pragma unroll
            for (int o = 16; o > 0; o >>= 1) s += __shfl_xor_sync(0xffffffffu, s, o);
            if (lid == 0) atomicMax(&sbest, packSI(s - __ldg(&g_halfcsq[m]), m));
        }
        __syncthreads();
        if (tid == 0)
            g_idx[row] = (int)(0xFFFFFFFFu - (unsigned)(sbest & 0xFFFFFFFFull));
    }
}

__global__ void k_gather(const float* __restrict__ cb, float* __restrict__ out,
                         float* __restrict__ idx_out) {
    int n = blockIdx.x;
    int idx = g_idx[n];
    const float4* src = (const float4*)(cb + (size_t)idx * D);
    float4* dst = (float4*)(out + (size_t)n * D);
    dst[threadIdx.x] = src[threadIdx.x];
    if (threadIdx.x == 0 && idx_out) idx_out[n] = (float)idx;
}

// ---------------- launch ----------------------------------------------------
extern "C" void kernel_launch(void* const* d_in, const int* in_sizes, int n_in,
                              void* d_out, int out_size) {
    const float* emb = (const float*)d_in[0];   // [65536, 512] f32
    const float* cb  = (const float*)d_in[1];   // [4096, 512]  f32
    float* out = (float*)d_out;

    float* idx_out = nullptr;
    long long need = (long long)NROWS * D + NROWS;
    if ((long long)out_size >= need) idx_out = out + (size_t)NROWS * D;

    cudaFuncSetAttribute(k_gemm, cudaFuncAttributeMaxDynamicSharedMemorySize, SMEM_TOTAL);

    k_init<<<1, 32>>>();
    k_quant_a<<<NROWS / 8, 256>>>(emb);
    k_quant_b<<<MCODES / 8, 256>>>(cb);

    dim3 grid(NT_C, NT_R);                      // (32, 512), ct fastest
    k_gemm<<<grid, 128, SMEM_TOTAL>>>();

    k_reduce<<<NROWS / 8, 256>>>();
    k_rescue<<<4096, 256>>>(emb, cb);
    k_gather<<<NROWS, 128>>>(cb, out, idx_out);
}

// round 13
// speedup vs baseline: 2.2983x; 1.1331x over previous
#include <cuda_runtime.h>
#include <cstdint>

#define D        512
#define NROWS    65536
#define MCODES   4096
#define BM       128
#define BN       128
#define NKC32    16              // k32 blocks (quant layout)
#define NST      8               // BK=64 stages
#define NT_R     512
#define NT_C     32
#define NGRP     64              // 64-col groups per row
#define THRESH   2.5f

// ---------------- scratch (device globals) -----------------------------------
#define A_BLK 4096               // 128 rows x 32 int8 per (rt,kc32)
#define B_BLK 4096
__device__ __align__(128) unsigned char qA[(size_t)NT_R * NKC32 * A_BLK]; // 32MB
__device__ __align__(128) unsigned char qB[(size_t)NT_C * NKC32 * B_BLK]; // 2MB

__device__ float              g_sA[NROWS];
__device__ float              g_sB[MCODES];
__device__ float              g_halfcsq[MCODES];
__device__ unsigned long long g_cand[(size_t)NROWS * NGRP * 2];  // 67MB
__device__ int                g_idx[NROWS];
__device__ int                g_flag_count;
__device__ int                g_flag_list[NROWS];

// ---------------- helpers ----------------------------------------------------
__device__ __forceinline__ unsigned int f2sortable(float f) {
    unsigned int u = __float_as_uint(f);
    return (u & 0x80000000u) ? ~u : (u | 0x80000000u);
}
__device__ __forceinline__ float sortable2f(unsigned int u) {
    unsigned int b = (u & 0x80000000u) ? (u ^ 0x80000000u) : ~u;
    return __uint_as_float(b);
}
__device__ __forceinline__ unsigned long long packSI(float s, int col) {
    return ((unsigned long long)f2sortable(s) << 32) |
           (unsigned long long)(0xFFFFFFFFu - (unsigned)col);
}
__device__ __forceinline__ void top2merge(unsigned long long& b1, unsigned long long& b2,
                                          unsigned long long o1, unsigned long long o2) {
    if (o1 > b1) { b2 = (b1 > o2) ? b1 : o2; b1 = o1; }
    else if (o1 > b2) { b2 = o1; }
}
__device__ __forceinline__ uint32_t smem_u32(const void* p) {
    uint32_t a;
    asm("{ .reg .u64 t; cvta.to.shared.u64 t, %1; cvt.u32.u64 %0, t; }" : "=r"(a) : "l"(p));
    return a;
}

// ---------------- cp.async / ldmatrix / mma ----------------------------------
__device__ __forceinline__ void cp16(uint32_t dst, const void* src) {
    asm volatile("cp.async.cg.shared.global [%0], [%1], 16;" :: "r"(dst), "l"(src) : "memory");
}
#define CP_COMMIT() asm volatile("cp.async.commit_group;" ::: "memory")
#define CP_WAIT(N)  asm volatile("cp.async.wait_group %0;" :: "n"(N) : "memory")

#define LDM4(r, addr) \
    asm volatile("ldmatrix.sync.aligned.m8n8.x4.shared.b16 {%0,%1,%2,%3}, [%4];" \
        : "=r"((r)[0]), "=r"((r)[1]), "=r"((r)[2]), "=r"((r)[3]) : "r"(addr))

#define MMAI8(d, a, b0_, b1_) \
    asm volatile("mma.sync.aligned.m16n8k32.row.col.s32.s8.s8.s32 " \
        "{%0,%1,%2,%3},{%4,%5,%6,%7},{%8,%9},{%0,%1,%2,%3};" \
        : "+r"((d)[0]), "+r"((d)[1]), "+r"((d)[2]), "+r"((d)[3]) \
        : "r"((a)[0]), "r"((a)[1]), "r"((a)[2]), "r"((a)[3]), "r"(b0_), "r"(b1_))

// ---------------- stage layout -----------------------------------------------
// stage = [A slice0 4K][A slice1 4K][B slice0 4K][B slice1 4K]
#define STG    16384
#define NSTAGE 4
#define SMEM_TOTAL (NSTAGE * STG)   // 65536

// ---------------- quantization (single digit) --------------------------------
__device__ __forceinline__ uint32_t pack4(int q0, int q1, int q2, int q3) {
    return (uint32_t)(q0 & 0xFF) | ((uint32_t)(q1 & 0xFF) << 8) |
           ((uint32_t)(q2 & 0xFF) << 16) | ((uint32_t)(q3 & 0xFF) << 24);
}

__device__ __forceinline__ void quant_row(const float* __restrict__ X, int row,
                                          unsigned char* __restrict__ pq,
                                          float* __restrict__ scale_out,
                                          float* __restrict__ halfcsq_out) {
    const int lane = threadIdx.x & 31;
    const float4* xp = (const float4*)(X + (size_t)row * D + lane * 16);
    float4 v[4];
    float amax = 0.f, ssq = 0.f;
    #pragma unroll
    for (int i = 0; i < 4; ++i) {
        v[i] = xp[i];
        amax = fmaxf(amax, fmaxf(fmaxf(fabsf(v[i].x), fabsf(v[i].y)),
                                 fmaxf(fabsf(v[i].z), fabsf(v[i].w))));
        if (halfcsq_out)
            ssq += v[i].x * v[i].x + v[i].y * v[i].y + v[i].z * v[i].z + v[i].w * v[i].w;
    }
    #pragma unroll
    for (int o = 16; o > 0; o >>= 1) {
        amax = fmaxf(amax, __shfl_xor_sync(0xffffffffu, amax, o));
        if (halfcsq_out) ssq += __shfl_xor_sync(0xffffffffu, ssq, o);
    }
    amax = fmaxf(amax, 1e-30f);
    const float inv = 127.f / amax;
    uint32_t H[4];
    #pragma unroll
    for (int i = 0; i < 4; ++i) {
        float f[4] = {v[i].x, v[i].y, v[i].z, v[i].w};
        int qh[4];
        #pragma unroll
        for (int j = 0; j < 4; ++j) {
            qh[j] = __float2int_rn(f[j] * inv);
            qh[j] = max(-127, min(127, qh[j]));
        }
        H[i] = pack4(qh[0], qh[1], qh[2], qh[3]);
    }
    const int rt  = row >> 7;
    const int rIn = row & 127;
    const int kc  = lane >> 1;
    const int c   = lane & 1;
    const size_t off = (size_t)(rt * NKC32 + kc) * 4096 + (size_t)(c * 128 + rIn) * 16;
    *(uint4*)(pq + off) = make_uint4(H[0], H[1], H[2], H[3]);
    if (lane == 0) {
        scale_out[row] = amax / 127.f;
        if (halfcsq_out) halfcsq_out[row] = 0.5f * ssq;
    }
}

__global__ void k_quant_a(const float* __restrict__ A) {
    int row = blockIdx.x * 8 + (threadIdx.x >> 5);
    if (row < NROWS) quant_row(A, row, qA, g_sA, nullptr);
}
__global__ void k_quant_b(const float* __restrict__ B) {
    int row = blockIdx.x * 8 + (threadIdx.x >> 5);
    if (row < MCODES) quant_row(B, row, qB, g_sB, g_halfcsq);
}

__global__ void k_init() { if (threadIdx.x == 0) g_flag_count = 0; }

// ---------------- main GEMM: single-product int8, BK=64 stages ---------------
// 128 thr (4 warps, 2x2), warp tile 64x64, CTA 128x128, 2 CTAs/SM.
// Per stage per warp: 16 LDSM + 64 straight-line mmas; no register copies.
__global__ void __launch_bounds__(128, 2)
k_gemm() {
    extern __shared__ char smem[];
    const uint32_t sb = smem_u32(smem);
    const int tid  = threadIdx.x;
    const int wid  = tid >> 5;
    const int lane = tid & 31;
    const int ct = blockIdx.x;           // 0..31 fastest -> B fully L2-resident
    const int rt = blockIdx.y;           // 0..511
    const int wr = wid >> 1;             // 0..1 -> rows wr*64..+63
    const int wc = wid & 1;              // 0..1 -> cols wc*64..+63

    const unsigned char* aP = qA + (size_t)(rt * NKC32) * A_BLK;
    const unsigned char* bP = qB + (size_t)(ct * NKC32) * B_BLK;

    // stage s <- k32 blocks {2s, 2s+1} (8KB contiguous per plane)
    auto load_stage = [&](int s) {
        const uint32_t st = sb + (s & (NSTAGE - 1)) * STG;
        const uint32_t o = tid * 16;               // 0..2047
        const unsigned char* pa = aP + (size_t)(2 * s) * A_BLK;
        const unsigned char* pb = bP + (size_t)(2 * s) * B_BLK;
        #pragma unroll
        for (int i = 0; i < 4; ++i)
            cp16(st + o + i * 2048, pa + o + i * 2048);
        #pragma unroll
        for (int i = 0; i < 4; ++i)
            cp16(st + 8192 + o + i * 2048, pb + o + i * 2048);
    };

    // ldmatrix lane address pieces (validated fragment mapping)
    const int mtx = lane >> 3;
    const uint32_t aOff = (uint32_t)((mtx >> 1) * 2048 +
                          (wr * 64 + (mtx & 1) * 8 + (lane & 7)) * 16);
    const uint32_t bOff = (uint32_t)(8192 + (mtx & 1) * 2048 +
                          (wc * 64 + (mtx >> 1) * 8 + (lane & 7)) * 16);

    int acc[4][8][4];
    #pragma unroll
    for (int m = 0; m < 4; ++m)
        #pragma unroll
        for (int n = 0; n < 8; ++n)
            #pragma unroll
            for (int q = 0; q < 4; ++q) acc[m][n][q] = 0;

    load_stage(0); CP_COMMIT();
    load_stage(1); CP_COMMIT();
    load_stage(2); CP_COMMIT();

    #pragma unroll 1
    for (int s = 0; s < NST; ++s) {
        if (s < NST - 2)       { CP_WAIT(2); }
        else if (s == NST - 2) { CP_WAIT(1); }
        else                   { CP_WAIT(0); }
        __syncthreads();
        // issue next stage AFTER the barrier: overwritten stage (s-1)&3 is
        // guaranteed fully read by all warps (they read it during iter s-1).
        if (s + 3 < NST) { load_stage(s + 3); CP_COMMIT(); }

        const uint32_t st = sb + (s & (NSTAGE - 1)) * STG;
        uint32_t fa0[4][4], fb0[4][4], fa1[4][4], fb1[4][4];
        #pragma unroll
        for (int m = 0; m < 4; ++m) LDM4(fa0[m], st + aOff + (uint32_t)(m * 256));
        #pragma unroll
        for (int j = 0; j < 4; ++j) LDM4(fb0[j], st + bOff + (uint32_t)(j * 256));
        #pragma unroll
        for (int m = 0; m < 4; ++m) LDM4(fa1[m], st + aOff + 4096u + (uint32_t)(m * 256));
        #pragma unroll
        for (int j = 0; j < 4; ++j) LDM4(fb1[j], st + bOff + 4096u + (uint32_t)(j * 256));

        // slice 0: 32 mmas, all-distinct accumulators
        #pragma unroll
        for (int m = 0; m < 4; ++m)
            #pragma unroll
            for (int j = 0; j < 4; ++j) {
                MMAI8(acc[m][2 * j],     fa0[m], fb0[j][0], fb0[j][1]);
                MMAI8(acc[m][2 * j + 1], fa0[m], fb0[j][2], fb0[j][3]);
            }
        // slice 1: 32 more (same accs, 32-mma reuse distance)
        #pragma unroll
        for (int m = 0; m < 4; ++m)
            #pragma unroll
            for (int j = 0; j < 4; ++j) {
                MMAI8(acc[m][2 * j],     fa1[m], fb1[j][0], fb1[j][1]);
                MMAI8(acc[m][2 * j + 1], fa1[m], fb1[j][2], fb1[j][3]);
            }
    }

    // ---- epilogue: per-row top2 over this warp's 64 cols (= one group) ----
    const int tig = lane & 3;
    const int colBase = ct * BN + wc * 64 + tig * 2;
    float sb2[8][2], hc[8][2];
    #pragma unroll
    for (int nf = 0; nf < 8; ++nf) {
        sb2[nf][0] = __ldg(&g_sB[colBase + nf * 8]);
        sb2[nf][1] = __ldg(&g_sB[colBase + nf * 8 + 1]);
        hc[nf][0]  = __ldg(&g_halfcsq[colBase + nf * 8]);
        hc[nf][1]  = __ldg(&g_halfcsq[colBase + nf * 8 + 1]);
    }
    #pragma unroll
    for (int m = 0; m < 4; ++m) {
        #pragma unroll
        for (int rv = 0; rv < 2; ++rv) {
            const int row = rt * BM + wr * 64 + m * 16 + (lane >> 2) + rv * 8;
            const float sa = __ldg(&g_sA[row]);
            unsigned long long b1 = 0ull, b2 = 0ull;
            #pragma unroll
            for (int nf = 0; nf < 8; ++nf)
                #pragma unroll
                for (int q = 0; q < 2; ++q) {
                    float s = sa * sb2[nf][q] * (float)acc[m][nf][2 * rv + q] - hc[nf][q];
                    top2merge(b1, b2, packSI(s, colBase + nf * 8 + q), 0ull);
                }
            #pragma unroll
            for (int o = 1; o < 4; o <<= 1) {
                unsigned long long o1 = __shfl_xor_sync(0xffffffffu, b1, o);
                unsigned long long o2 = __shfl_xor_sync(0xffffffffu, b2, o);
                top2merge(b1, b2, o1, o2);
            }
            if (tig == 0) {
                const size_t base = ((size_t)row * NGRP + (ct * 2 + wc)) * 2;
                g_cand[base]     = b1;
                g_cand[base + 1] = b2;
            }
        }
    }
}

// ---------------- reduce (warp per row) --------------------------------------
__global__ void k_reduce() {
    const int lane = threadIdx.x & 31;
    const int row  = blockIdx.x * 8 + (threadIdx.x >> 5);
    if (row >= NROWS) return;
    const unsigned long long* c = g_cand + (size_t)row * NGRP * 2;
    unsigned long long b1 = 0ull, b2 = 0ull;
    #pragma unroll
    for (int k = 0; k < 4; ++k) {
        unsigned long long v = c[lane + 32 * k];
        top2merge(b1, b2, v, 0ull);
    }
    #pragma unroll
    for (int o = 16; o > 0; o >>= 1) {
        unsigned long long o1 = __shfl_xor_sync(0xffffffffu, b1, o);
        unsigned long long o2 = __shfl_xor_sync(0xffffffffu, b2, o);
        top2merge(b1, b2, o1, o2);
    }
    if (lane == 0) {
        g_idx[row] = (int)(0xFFFFFFFFu - (unsigned)(b1 & 0xFFFFFFFFull));
        float s1 = sortable2f((unsigned)(b1 >> 32));
        float s2 = sortable2f((unsigned)(b2 >> 32));
        if (s1 - s2 < THRESH) {
            int slot = atomicAdd(&g_flag_count, 1);
            if (slot < NROWS) g_flag_list[slot] = row;
        }
    }
}

// ---------------- rescue: exact fp32 re-rank of candidate set ----------------
#define CLIST_MAX 128
__global__ void __launch_bounds__(256)
k_rescue(const float* __restrict__ A, const float* __restrict__ B) {
    __shared__ float xrow[D];
    __shared__ unsigned long long sbest;
    __shared__ int clist[CLIST_MAX];
    __shared__ int ccount;
    const int tid = threadIdx.x, wid = tid >> 5, lid = tid & 31;
    const int count = min(g_flag_count, NROWS);
    for (int i = blockIdx.x; i < count; i += gridDim.x) {
        const int row = g_flag_list[i];
        __syncthreads();
        if (tid == 0) { sbest = 0ull; ccount = 0; }
        for (int j = tid; j < D; j += 256) xrow[j] = A[(size_t)row * D + j];
        __syncthreads();
        const unsigned long long* c = g_cand + (size_t)row * NGRP * 2;
        unsigned long long amax = 0ull;
        for (int e = tid; e < NGRP * 2; e += 256) {
            unsigned long long v = c[e];
            if (v > amax) amax = v;
        }
        atomicMax(&sbest, amax);
        __syncthreads();
        const unsigned thrU = f2sortable(sortable2f((unsigned)(sbest >> 32)) - THRESH);
        for (int e = tid; e < NGRP * 2; e += 256) {
            unsigned long long v = c[e];
            if ((unsigned)(v >> 32) >= thrU) {
                int slot = atomicAdd(&ccount, 1);
                if (slot < CLIST_MAX)
                    clist[slot] = (int)(0xFFFFFFFFu - (unsigned)(v & 0xFFFFFFFFull));
            }
        }
        __syncthreads();
        if (tid == 0) sbest = 0ull;
        __syncthreads();
        const int nc = min(ccount, CLIST_MAX);
        for (int k = wid; k < nc; k += 8) {
            const int m = clist[k];
            const float* cp = B + (size_t)m * D;
            float s = 0.f;
            #pragma unroll
            for (int t = 0; t < 4; ++t) {
                float4 cv = *(const float4*)(cp + t * 128 + lid * 4);
                float4 xv = *(const float4*)(xrow + t * 128 + lid * 4);
                s += cv.x * xv.x + cv.y * xv.y + cv.z * xv.z + cv.w * xv.w;
            }
            #pragma unroll
            for (int o = 16; o > 0; o >>= 1) s += __shfl_xor_sync(0xffffffffu, s, o);
            if (lid == 0) atomicMax(&sbest, packSI(s - __ldg(&g_halfcsq[m]), m));
        }
        __syncthreads();
        if (tid == 0)
            g_idx[row] = (int)(0xFFFFFFFFu - (unsigned)(sbest & 0xFFFFFFFFull));
    }
}

__global__ void k_gather(const float* __restrict__ cb, float* __restrict__ out,
                         float* __restrict__ idx_out) {
    int n = blockIdx.x;
    int idx = g_idx[n];
    const float4* src = (const float4*)(cb + (size_t)idx * D);
    float4* dst = (float4*)(out + (size_t)n * D);
    dst[threadIdx.x] = src[threadIdx.x];
    if (threadIdx.x == 0 && idx_out) idx_out[n] = (float)idx;
}

// ---------------- launch ----------------------------------------------------
extern "C" void kernel_launch(void* const* d_in, const int* in_sizes, int n_in,
                              void* d_out, int out_size) {
    const float* emb = (const float*)d_in[0];   // [65536, 512] f32
    const float* cb  = (const float*)d_in[1];   // [4096, 512]  f32
    float* out = (float*)d_out;

    float* idx_out = nullptr;
    long long need = (long long)NROWS * D + NROWS;
    if ((long long)out_size >= need) idx_out = out + (size_t)NROWS * D;

    cudaFuncSetAttribute(k_gemm, cudaFuncAttributeMaxDynamicSharedMemorySize, SMEM_TOTAL);

    k_init<<<1, 32>>>();
    k_quant_a<<<NROWS / 8, 256>>>(emb);
    k_quant_b<<<MCODES / 8, 256>>>(cb);

    dim3 grid(NT_C, NT_R);                      // (32, 512), ct fastest
    k_gemm<<<grid, 128, SMEM_TOTAL>>>();

    k_reduce<<<NROWS / 8, 256>>>();
    k_rescue<<<4096, 256>>>(emb, cb);
    k_gather<<<NROWS, 128>>>(cb, out, idx_out);
}